// round 13
// baseline (speedup 1.0000x reference)
#include <cuda_runtime.h>

#define DEPTH 10
#define WIDTH 512
#define LVL_ELEMS (DEPTH * WIDTH)   // 5120 floats per (b,t)
#define TPB 128                     // 4 columns per thread
#define BT_PER_BLK 2

__device__ __forceinline__ float sigmoidf(float v) {
    // sigmoid(x) = 0.5 * tanh(x/2) + 0.5 — single MUFU (HW tanh) + MUL + FMA
    float t;
    asm("tanh.approx.f32 %0, %1;" : "=f"(t) : "f"(v * 0.5f));
    return fmaf(t, 0.5f, 0.5f);
}

// Streaming LDG.128 with evict-first policy + 256B L2 prefetch hint.
__device__ __forceinline__ float4 ldg_stream(const float4* p) {
    float4 v;
    asm("ld.global.cs.L2::256B.v4.f32 {%0,%1,%2,%3}, [%4];"
        : "=f"(v.x), "=f"(v.y), "=f"(v.z), "=f"(v.w) : "l"(p));
    return v;
}

template <int W>
__device__ __forceinline__ float allred(float v) {
    #pragma unroll
    for (int ofs = 1; ofs < W; ofs <<= 1)
        v += __shfl_xor_sync(0xffffffffu, v, ofs);
    return v;
}

__global__ void __launch_bounds__(TPB, 10)
NCT_82162724372482_kernel(const float* __restrict__ x, float* __restrict__ out) {
    __shared__ float ws0[4], ws1[4], wsf[4];

    const int tid  = threadIdx.x;            // column group: cols [4*tid, 4*tid+3]
    const int warp = tid >> 5;
    const int lane = tid & 31;

    // Sequential 2-bt coarsening: same 48-reg body reused; unroll 1 prevents
    // ptxas from software-pipelining iteration 2's loads (the R8 reg blow-up).
    #pragma unroll 1
    for (int k = 0; k < BT_PER_BLK; ++k) {
        const int bt = blockIdx.x * BT_PER_BLK + k;

        const float4* __restrict__ x4 =
            reinterpret_cast<const float4*>(x) + (size_t)bt * (LVL_ELEMS / 4) + tid;

        // Front-batched loads: 10 independent LDG.128 (MLP=10)
        float4 v[DEPTH];
        #pragma unroll
        for (int j = 0; j < DEPTH; ++j) v[j] = ldg_stream(&x4[j * (WIDTH / 4)]);

        // Sigmoids + per-thread (4-column) sums per level
        float sum4[DEPTH];
        float4 sg8, sg9;
        #pragma unroll
        for (int j = 0; j < DEPTH; ++j) {
            float a = sigmoidf(v[j].x);
            float b = sigmoidf(v[j].y);
            float c = sigmoidf(v[j].z);
            float d = sigmoidf(v[j].w);
            sum4[j] = (a + b) + (c + d);
            if (j == 8) sg8 = make_float4(a, b, c, d);
            if (j == 9) sg9 = make_float4(a, b, c, d);
        }

        // d1[j] = mean of level-j sigmoids over this thread's segment.
        float d1[8];
        d1[7] = sum4[7] * 0.25f;                       // 1 thread
        d1[6] = allred<2>(sum4[6])  * (1.0f / 8.0f);   // 2 threads
        d1[5] = allred<4>(sum4[5])  * (1.0f / 16.0f);
        d1[4] = allred<8>(sum4[4])  * (1.0f / 32.0f);
        d1[3] = allred<16>(sum4[3]) * (1.0f / 64.0f);
        d1[2] = allred<32>(sum4[2]) * (1.0f / 128.0f); // full warp

        // Levels 0 and 1 span multiple warps: warp-sum then tiny smem combine.
        // (Barrier below also isolates smem reuse across the two bt phases.)
        float w1 = allred<32>(sum4[1]);
        float w0 = allred<32>(sum4[0]);
        __syncthreads();   // protect ws* from previous iteration's readers
        if (lane == 0) { ws1[warp] = w1; ws0[warp] = w0; }
        __syncthreads();
        d1[1] = (ws1[warp] + ws1[warp ^ 1]) * (1.0f / 256.0f);
        d1[0] = ((ws0[0] + ws0[1]) + (ws0[2] + ws0[3])) * (1.0f / 512.0f);

        // Path product for levels 0..6 — identical for all 4 leaves.
        float common = 1.0f;
        #pragma unroll
        for (int j = 0; j <= 6; ++j) {
            int bit = (tid >> (6 - j)) & 1;
            common *= bit ? d1[j] : (1.0f - d1[j]);
        }

        // Levels 7..9 in closed form over the 4 leaves.
        float d8a  = (sg8.x + sg8.y) * 0.5f;
        float d8b  = (sg8.z + sg8.w) * 0.5f;
        float left  = (1.0f - d8a) * sg9.x + d8a * sg9.y;
        float right = (1.0f - d8b) * sg9.z + d8b * sg9.w;
        float tv = common * ((1.0f - d1[7]) * left + d1[7] * right);

        // Block reduction -> one scalar per (b,t)
        tv = allred<32>(tv);
        if (lane == 0) wsf[warp] = tv;
        __syncthreads();
        if (tid == 0) out[bt] = (wsf[0] + wsf[1]) + (wsf[2] + wsf[3]);
    }
}

extern "C" void kernel_launch(void* const* d_in, const int* in_sizes, int n_in,
                              void* d_out, int out_size) {
    const float* x = (const float*)d_in[0];
    float* out = (float*)d_out;
    const int n_bt = in_sizes[0] / LVL_ELEMS;   // BATCH * NUM_TREES = 16384
    NCT_82162724372482_kernel<<<n_bt / BT_PER_BLK, TPB>>>(x, out);
}

// round 14
// speedup vs baseline: 1.0322x; 1.0322x over previous
#include <cuda_runtime.h>

#define DEPTH 10
#define WIDTH 512
#define LVL_ELEMS (DEPTH * WIDTH)   // 5120 floats per (b,t)
#define TPB 128                     // 4 columns per thread

__device__ __forceinline__ float sigmoidf(float v) {
    // sigmoid(x) = 0.5 * tanh(x/2) + 0.5 — single MUFU (HW tanh) + MUL + FMA
    float t;
    asm("tanh.approx.f32 %0, %1;" : "=f"(t) : "f"(v * 0.5f));
    return fmaf(t, 0.5f, 0.5f);
}

// Streaming LDG.128 with evict-first policy + 256B L2 prefetch hint.
__device__ __forceinline__ float4 ldg_stream(const float4* p) {
    float4 v;
    asm("ld.global.cs.L2::256B.v4.f32 {%0,%1,%2,%3}, [%4];"
        : "=f"(v.x), "=f"(v.y), "=f"(v.z), "=f"(v.w) : "l"(p));
    return v;
}

template <int W>
__device__ __forceinline__ float allred(float v) {
    #pragma unroll
    for (int ofs = 1; ofs < W; ofs <<= 1)
        v += __shfl_xor_sync(0xffffffffu, v, ofs);
    return v;
}

__global__ void __launch_bounds__(TPB, 10)
NCT_82162724372482_kernel(const float* __restrict__ x, float* __restrict__ out) {
    __shared__ float ws0[4], ws1[4], wsf[4];

    const int bt   = blockIdx.x;            // b*NUM_TREES + t
    const int tid  = threadIdx.x;           // column group: cols [4*tid, 4*tid+3]
    const int warp = tid >> 5;
    const int lane = tid & 31;

    const float4* __restrict__ x4 =
        reinterpret_cast<const float4*>(x) + (size_t)bt * (LVL_ELEMS / 4) + tid;

    // Front-batched loads: 10 independent LDG.128 (MLP=10)
    float4 v[DEPTH];
    #pragma unroll
    for (int j = 0; j < DEPTH; ++j) v[j] = ldg_stream(&x4[j * (WIDTH / 4)]);

    // Sigmoids + per-thread (4-column) sums per level
    float sum4[DEPTH];
    float4 sg8, sg9;
    #pragma unroll
    for (int j = 0; j < DEPTH; ++j) {
        float a = sigmoidf(v[j].x);
        float b = sigmoidf(v[j].y);
        float c = sigmoidf(v[j].z);
        float d = sigmoidf(v[j].w);
        sum4[j] = (a + b) + (c + d);
        if (j == 8) sg8 = make_float4(a, b, c, d);
        if (j == 9) sg9 = make_float4(a, b, c, d);
    }

    // d1[j] = mean of level-j sigmoids over the segment containing this
    // thread's columns. Segment at level j has 512>>j columns = 128>>j threads.
    float d1[8];
    d1[7] = sum4[7] * 0.25f;                       // 1 thread
    d1[6] = allred<2>(sum4[6])  * (1.0f / 8.0f);   // 2 threads
    d1[5] = allred<4>(sum4[5])  * (1.0f / 16.0f);
    d1[4] = allred<8>(sum4[4])  * (1.0f / 32.0f);
    d1[3] = allred<16>(sum4[3]) * (1.0f / 64.0f);
    d1[2] = allred<32>(sum4[2]) * (1.0f / 128.0f); // full warp

    // Levels 0 and 1 span multiple warps: warp-sum then tiny smem combine
    float w1 = allred<32>(sum4[1]);
    float w0 = allred<32>(sum4[0]);
    if (lane == 0) { ws1[warp] = w1; ws0[warp] = w0; }
    __syncthreads();
    d1[1] = (ws1[warp] + ws1[warp ^ 1]) * (1.0f / 256.0f);
    d1[0] = ((ws0[0] + ws0[1]) + (ws0[2] + ws0[3])) * (1.0f / 512.0f);

    // Path product for levels 0..6 — identical for all 4 leaves of this thread.
    // Leaf s = 4*tid + k; bit at level j is (tid >> (6-j)) & 1 for j<=6.
    float common = 1.0f;
    #pragma unroll
    for (int j = 0; j <= 6; ++j) {
        int bit = (tid >> (6 - j)) & 1;
        common *= bit ? d1[j] : (1.0f - d1[j]);
    }

    // Close the last 3 levels in closed form over the 4 leaves:
    //   level 8 means: d8a = mean(sg8.x, sg8.y) [leaves k=0,1], d8b [k=2,3]
    //   level 9 weight: sig9 per leaf
    float d8a  = (sg8.x + sg8.y) * 0.5f;
    float d8b  = (sg8.z + sg8.w) * 0.5f;
    float left  = (1.0f - d8a) * sg9.x + d8a * sg9.y;  // k=0,1 (level-7 bit = 0)
    float right = (1.0f - d8b) * sg9.z + d8b * sg9.w;  // k=2,3 (level-7 bit = 1)
    float tv = common * ((1.0f - d1[7]) * left + d1[7] * right);

    // Block reduction -> one scalar per (b,t)
    tv = allred<32>(tv);
    if (lane == 0) wsf[warp] = tv;
    __syncthreads();
    if (tid == 0) out[bt] = (wsf[0] + wsf[1]) + (wsf[2] + wsf[3]);
}

extern "C" void kernel_launch(void* const* d_in, const int* in_sizes, int n_in,
                              void* d_out, int out_size) {
    const float* x = (const float*)d_in[0];
    float* out = (float*)d_out;
    const int n_bt = in_sizes[0] / LVL_ELEMS;   // BATCH * NUM_TREES = 16384
    NCT_82162724372482_kernel<<<n_bt, TPB>>>(x, out);
}